// round 7
// baseline (speedup 1.0000x reference)
#include <cuda_runtime.h>
#include <math.h>

#define NN    128
#define MM    64
#define MM2   76            // padded capacity (4-aligned segments)
#define MMP   76            // row stride in floats (16B multiple)
#define NG    20
#define NA    10
#define FPS   600

#define RSQRTPI_F 0.56418958354775628695f
#define LN2_F     0.69314718055994530942f
#define HLOG2E    0.72134752044448170368f   // 0.5 * log2(e)

__constant__ float c_angw[NA] = {1.f,1.f,1.f,1.f,1.f,2.f,1.f,2.f,2.f,1.f};
__constant__ int c_ci[6] = {0,0,0,1,1,2};
__constant__ int c_cj[6] = {1,2,3,2,3,3};

__constant__ float c_logoff[NG] = {
    -1.2039728043f, -0.5108256238f, -0.1053605157f,  0.1823215568f,
     0.4054651081f,  0.5877866649f,  0.7419373447f,  0.8754687374f,
     0.9932517730f,  1.0986122887f,  1.1939224685f,  1.2809338455f,
     1.3609765531f,  1.4350845253f,  1.5040773968f,  1.5686159179f,
     1.6292405397f,  1.6863989543f,  1.7404661748f,  1.7917594692f };
__constant__ float c_invoff[NG] = {
    3.3333333333f, 1.6666666667f, 1.1111111111f, 0.8333333333f,
    0.6666666667f, 0.5555555556f, 0.4761904762f, 0.4166666667f,
    0.3703703704f, 0.3333333333f, 0.3030303030f, 0.2777777778f,
    0.2564102564f, 0.2380952381f, 0.2222222222f, 0.2083333333f,
    0.1960784314f, 0.1851851852f, 0.1754385965f, 0.1666666667f };

__device__ __forceinline__ float ex2f(float x)  { float y; asm("ex2.approx.ftz.f32 %0, %1;"   : "=f"(y) : "f"(x)); return y; }
__device__ __forceinline__ float lg2f(float x)  { float y; asm("lg2.approx.ftz.f32 %0, %1;"   : "=f"(y) : "f"(x)); return y; }
__device__ __forceinline__ float rcpf(float x)  { float y; asm("rcp.approx.ftz.f32 %0, %1;"   : "=f"(y) : "f"(x)); return y; }
__device__ __forceinline__ float rsqf(float x)  { float y; asm("rsqrt.approx.ftz.f32 %0, %1;" : "=f"(y) : "f"(x)); return y; }

__device__ __forceinline__ float pick4(const float4 t, int i) {
    return (i == 0) ? t.x : ((i == 1) ? t.y : ((i == 2) ? t.z : t.w));
}

__global__ __launch_bounds__(256, 6)
void fp_kernel(const float* __restrict__ coords,
               const int*   __restrict__ charges,
               const int*   __restrict__ counts,
               const int*   __restrict__ neigh,
               float*       __restrict__ out)
{
    const int atom = blockIdx.x;
    const int b = atom >> 7;              // NN = 128
    const int n = atom & 127;
    const int tid = threadIdx.x;

    float* outp = out + (size_t)atom * FPS;

    if (n >= counts[b]) {
        float4* o4 = (float4*)outp;
        for (int o = tid; o < FPS / 4; o += 256) o4[o] = make_float4(0.f,0.f,0.f,0.f);
        return;
    }

    __shared__ __align__(16) float s_rad[NG * MMP];   // [g][m]
    __shared__ __align__(16) float s_ang[NA * MMP];   // [a][m]
    __shared__ __align__(16) float4 s_t[NA * NG];     // per-species accumulators
    __shared__ float s_nbx[MM2], s_nby[MM2], s_nbz[MM2];
    __shared__ float s_mu[MM2], s_ni2s[MM2], s_k[MM2], s_invd[MM2];
    __shared__ int   s_wcnt[2][4];
    __shared__ int   s_seg4[4];           // 4-aligned segment ends (floats)

    // ---- defaults for padded slots (rad -> 0, ang -> 0) ----
    if (tid < MM2) {
        s_mu[tid] = 0.f; s_ni2s[tid] = 0.f; s_k[tid] = 0.f; s_invd[tid] = 0.f;
        s_nbx[tid] = 0.f; s_nby[tid] = 0.f; s_nbz[tid] = 0.f;
    }

    // ---- phase A: per-neighbour scalars + species ballots (threads 0..63) ----
    int my_sp = 0;
    unsigned bm0 = 0, bm1 = 0, bm2 = 0, bm3 = 0;
    float r_dx=0.f, r_dy=0.f, r_dz=0.f, r_mu=0.f, r_ni2s=0.f, r_k=0.f, r_invd=0.f;
    if (tid < MM) {
        const int w = tid >> 5;
        const int nbraw = neigh[(size_t)atom * MM + tid];
        const bool valid = nbraw >= 0;
        const int nb = valid ? nbraw : 0;

        const float ax = coords[(size_t)atom * 3 + 0];
        const float ay = coords[(size_t)atom * 3 + 1];
        const float az = coords[(size_t)atom * 3 + 2];
        const size_t nbase = ((size_t)b * NN + nb) * 3;
        float dx = ax - coords[nbase + 0];
        float dy = ay - coords[nbase + 1];
        float dz = az - coords[nbase + 2];
        if (!valid) { dx = 1.0f; dy = 1.0f; dz = 1.0f; }

        const float d2   = dx*dx + dy*dy + dz*dz;
        const float ivd  = rsqf(d2);                               // 1/d
        const float d    = d2 * ivd;
        const float rd2  = ivd * ivd;                              // 1/d^2
        const float sig2 = LN2_F * lg2f(fmaf(2.0f, rd2, 1.0f));    // log1p(2/d^2)
        const float mu   = fmaf(0.5f * LN2_F, lg2f(d2), -0.5f * sig2);
        const float dsw  = (d - 1.0f) * 0.2f;
        const float dsw2 = dsw * dsw;
        const float cut  = 1.0f - dsw2 * dsw * (10.0f - 15.0f*dsw + 6.0f*dsw2);

        const int z = charges[(size_t)b * NN + nb];
        my_sp = (z == 1) ? 0 : ((z == 6) ? 1 : ((z == 7) ? 2 : 3));

        r_dx = dx; r_dy = dy; r_dz = dz;
        r_mu = mu;
        r_ni2s = -HLOG2E * rcpf(sig2);
        r_k    = valid ? (cut * rsqf(sig2) * RSQRTPI_F) : 0.0f;
        r_invd = valid ? ivd : 0.0f;

        bm0 = __ballot_sync(0xffffffffu, my_sp == 0);
        bm1 = __ballot_sync(0xffffffffu, my_sp == 1);
        bm2 = __ballot_sync(0xffffffffu, my_sp == 2);
        bm3 = __ballot_sync(0xffffffffu, my_sp == 3);
        if ((tid & 31) == 0) {
            s_wcnt[w][0] = __popc(bm0);
            s_wcnt[w][1] = __popc(bm1);
            s_wcnt[w][2] = __popc(bm2);
            s_wcnt[w][3] = __popc(bm3);
        }
    }
    __syncthreads();

    // ---- scatter to species-sorted 4-aligned slots; publish segment ends ----
    if (tid < MM) {
        const int c0 = s_wcnt[0][0] + s_wcnt[1][0];
        const int c1 = s_wcnt[0][1] + s_wcnt[1][1];
        const int c2 = s_wcnt[0][2] + s_wcnt[1][2];
        const int c3 = s_wcnt[0][3] + s_wcnt[1][3];
        const int s1 = (c0 + 3) & ~3;
        const int s2 = (s1 + c1 + 3) & ~3;
        const int s3 = (s2 + c2 + 3) & ~3;
        const int base = (my_sp == 0) ? 0 : ((my_sp == 1) ? s1 : ((my_sp == 2) ? s2 : s3));
        const int w = tid >> 5;
        const int lane = tid & 31;
        const unsigned myb = (my_sp == 0) ? bm0 : ((my_sp == 1) ? bm1 : ((my_sp == 2) ? bm2 : bm3));
        int rank = __popc(myb & ((1u << lane) - 1u));
        if (w == 1) rank += s_wcnt[0][my_sp];
        const int pos = base + rank;
        s_nbx[pos] = r_dx; s_nby[pos] = r_dy; s_nbz[pos] = r_dz;
        s_mu[pos]  = r_mu; s_ni2s[pos] = r_ni2s;
        s_k[pos]   = r_k;  s_invd[pos] = r_invd;
        if (tid == 0) {
            s_seg4[0] = s1;
            s_seg4[1] = s2;
            s_seg4[2] = s3;
            s_seg4[3] = (s3 + c3 + 3) & ~3;
        }
    }
    __syncthreads();

    // ---- phase B: radial [g][m] (threads 0..151), angular [a][m] (152..227) ----
    if (tid < 2 * MM2) {
        const int m    = tid >> 1;
        const int half = tid & 1;
        const float mu   = s_mu[m];
        const float ni2s = s_ni2s[m];
        const float k    = s_k[m];
        const int g0 = half * 10;
        #pragma unroll
        for (int gg = 0; gg < 10; gg++) {
            const int g = g0 + gg;
            const float c = c_logoff[g] - mu;
            const float e = ex2f(c * c * ni2s);
            s_rad[g * MMP + m] = k * c_invoff[g] * e;
        }
    } else if (tid < 2 * MM2 + MM2) {
        const int m = tid - 2 * MM2;
        const float x = s_nbx[m], y = s_nby[m], zc = s_nbz[m];
        const float id = s_invd[m];
        const float i2 = id * id;
        const float i3 = i2 * id;
        const float i4 = i2 * i2;
        s_ang[0 * MMP + m] = i2;
        s_ang[1 * MMP + m] = i3 * x;
        s_ang[2 * MMP + m] = i3 * y;
        s_ang[3 * MMP + m] = i3 * zc;
        s_ang[4 * MMP + m] = i4 * x * x;
        s_ang[5 * MMP + m] = i4 * x * y;
        s_ang[6 * MMP + m] = i4 * y * y;
        s_ang[7 * MMP + m] = i4 * x * zc;
        s_ang[8 * MMP + m] = i4 * y * zc;
        s_ang[9 * MMP + m] = i4 * zc * zc;
    }
    __syncthreads();

    // ---- main loop (R3 shape): thread (a,g); 4 segments in float4 chunks ----
    if (tid < NA * NG) {
        const int a = tid / NG;
        const int g = tid - a * NG;
        const float4* __restrict__ angp = (const float4*)(s_ang + a * MMP);
        const float4* __restrict__ radp = (const float4*)(s_rad + g * MMP);
        const int e0 = s_seg4[0] >> 2;
        const int e1 = s_seg4[1] >> 2;
        const int e2 = s_seg4[2] >> 2;
        const int e3 = s_seg4[3] >> 2;

        float t0 = 0.f, t1 = 0.f, t2 = 0.f, t3 = 0.f;
        int c = 0;
        #pragma unroll 2
        for (; c < e0; ++c) {
            const float4 av = angp[c], rv = radp[c];
            t0 = fmaf(av.x, rv.x, t0); t0 = fmaf(av.y, rv.y, t0);
            t0 = fmaf(av.z, rv.z, t0); t0 = fmaf(av.w, rv.w, t0);
        }
        #pragma unroll 2
        for (; c < e1; ++c) {
            const float4 av = angp[c], rv = radp[c];
            t1 = fmaf(av.x, rv.x, t1); t1 = fmaf(av.y, rv.y, t1);
            t1 = fmaf(av.z, rv.z, t1); t1 = fmaf(av.w, rv.w, t1);
        }
        #pragma unroll 2
        for (; c < e2; ++c) {
            const float4 av = angp[c], rv = radp[c];
            t2 = fmaf(av.x, rv.x, t2); t2 = fmaf(av.y, rv.y, t2);
            t2 = fmaf(av.z, rv.z, t2); t2 = fmaf(av.w, rv.w, t2);
        }
        #pragma unroll 2
        for (; c < e3; ++c) {
            const float4 av = angp[c], rv = radp[c];
            t3 = fmaf(av.x, rv.x, t3); t3 = fmaf(av.y, rv.y, t3);
            t3 = fmaf(av.z, rv.z, t3); t3 = fmaf(av.w, rv.w, t3);
        }
        s_t[tid] = make_float4(t0, t1, t2, t3);
    }
    __syncthreads();

    // ---- epilogue: 150 float4 outputs ----
    float4* outp4 = (float4*)outp;
    for (int o4 = tid; o4 < FPS / 4; o4 += 256) {
        const int g4   = o4 % 5;
        const int rest = o4 / 5;
        const int mb   = rest % 10;
        const int l    = rest / 10;
        const int a0 = (l == 0) ? 0 : ((l == 1) ? 1 : 4);
        const int a1 = (l == 0) ? 1 : ((l == 1) ? 4 : 10);
        float4 val = make_float4(0.f, 0.f, 0.f, 0.f);
        if (mb < 4) {
            for (int a = a0; a < a1; a++) {
                const float4* tp = s_t + a * NG + g4 * 4;
                const float w = c_angw[a];
                float v;
                v = pick4(tp[0], mb); val.x = fmaf(w * v, v, val.x);
                v = pick4(tp[1], mb); val.y = fmaf(w * v, v, val.y);
                v = pick4(tp[2], mb); val.z = fmaf(w * v, v, val.z);
                v = pick4(tp[3], mb); val.w = fmaf(w * v, v, val.w);
            }
        } else {
            const int cidx = mb - 4;
            const int i = c_ci[cidx], j = c_cj[cidx];
            for (int a = a0; a < a1; a++) {
                const float4* tp = s_t + a * NG + g4 * 4;
                const float w2 = 2.0f * c_angw[a];
                val.x = fmaf(w2 * pick4(tp[0], i), pick4(tp[0], j), val.x);
                val.y = fmaf(w2 * pick4(tp[1], i), pick4(tp[1], j), val.y);
                val.z = fmaf(w2 * pick4(tp[2], i), pick4(tp[2], j), val.z);
                val.w = fmaf(w2 * pick4(tp[3], i), pick4(tp[3], j), val.w);
            }
        }
        outp4[o4] = val;
    }
}

extern "C" void kernel_launch(void* const* d_in, const int* in_sizes, int n_in,
                              void* d_out, int out_size) {
    const float* coords  = (const float*)d_in[0];
    const int*   charges = (const int*)d_in[1];
    const int*   counts  = (const int*)d_in[2];
    const int*   neigh   = (const int*)d_in[3];
    float* out = (float*)d_out;
    (void)n_in; (void)out_size;

    const int B = in_sizes[2];
    const int N = in_sizes[1] / B;
    dim3 grid(B * N);
    fp_kernel<<<grid, 256>>>(coords, charges, counts, neigh, out);
}

// round 8
// speedup vs baseline: 1.6105x; 1.6105x over previous
#include <cuda_runtime.h>
#include <math.h>

#define NN    128
#define MM    64
#define MM2   76            // padded neighbour capacity (segments 4-aligned), 76 floats = 19 float4
#define MMP   76            // ang row stride in floats (16B multiple)
#define MMR   77            // rad row stride in floats (odd -> conflict-free scalar reads)
#define NG    20
#define NA    10
#define FPS   600

#define SQRTPI_F 1.7724538509055160273f
#define HLOG2E   0.72134752044448170368f   // 0.5 * log2(e)

__constant__ float c_angw[NA] = {1.f,1.f,1.f,1.f,1.f,2.f,1.f,2.f,2.f,1.f};
__constant__ int c_ci[6] = {0,0,0,1,1,2};
__constant__ int c_cj[6] = {1,2,3,2,3,3};

// log(0.3*(g+1)) and 1/(0.3*(g+1)), g=0..19
__constant__ float c_logoff[NG] = {
    -1.2039728043f, -0.5108256238f, -0.1053605157f,  0.1823215568f,
     0.4054651081f,  0.5877866649f,  0.7419373447f,  0.8754687374f,
     0.9932517730f,  1.0986122887f,  1.1939224685f,  1.2809338455f,
     1.3609765531f,  1.4350845253f,  1.5040773968f,  1.5686159179f,
     1.6292405397f,  1.6863989543f,  1.7404661748f,  1.7917594692f };
__constant__ float c_invoff[NG] = {
    3.3333333333f, 1.6666666667f, 1.1111111111f, 0.8333333333f,
    0.6666666667f, 0.5555555556f, 0.4761904762f, 0.4166666667f,
    0.3703703704f, 0.3333333333f, 0.3030303030f, 0.2777777778f,
    0.2564102564f, 0.2380952381f, 0.2222222222f, 0.2083333333f,
    0.1960784314f, 0.1851851852f, 0.1754385965f, 0.1666666667f };

__device__ __forceinline__ float ex2f(float x) {
    float y;
    asm("ex2.approx.ftz.f32 %0, %1;" : "=f"(y) : "f"(x));
    return y;
}

__device__ __forceinline__ float pick4(const float4 t, int i) {
    return (i == 0) ? t.x : ((i == 1) ? t.y : ((i == 2) ? t.z : t.w));
}

__global__ __launch_bounds__(256, 6)
void fp_kernel(const float* __restrict__ coords,
               const int*   __restrict__ charges,
               const int*   __restrict__ counts,
               const int*   __restrict__ neigh,
               float*       __restrict__ out)
{
    const int atom = blockIdx.x;
    const int b = atom >> 7;              // NN = 128
    const int n = atom & 127;
    const int tid = threadIdx.x;

    float* outp = out + (size_t)atom * FPS;

    if (n >= counts[b]) {
        for (int o = tid; o < FPS; o += 256) outp[o] = 0.0f;
        return;
    }

    __shared__ __align__(16) float s_rad[NG * MMR];   // [g][m], stride 77
    __shared__ __align__(16) float s_ang[NA * MMP];   // [a][m], stride 76
    __shared__ float s_nbx[MM2], s_nby[MM2], s_nbz[MM2];
    __shared__ float s_mu[MM2], s_ni2s[MM2], s_k[MM2], s_invd[MM2];
    __shared__ int   s_wcnt[2][4];
    __shared__ int   s_seg4[5];           // 4-aligned segment starts
    __shared__ float4 s_t[NA * NG];

    // ---- defaults for padded slots (rad -> 0, ang -> 0) ----
    if (tid < MM2) {
        s_mu[tid] = 0.f; s_ni2s[tid] = 0.f; s_k[tid] = 0.f; s_invd[tid] = 0.f;
        s_nbx[tid] = 0.f; s_nby[tid] = 0.f; s_nbz[tid] = 0.f;
    }

    // ---- phase A: per-neighbour scalars + species ballots ----
    int my_sp = 0;
    unsigned bm0 = 0, bm1 = 0, bm2 = 0, bm3 = 0;
    float r_dx = 0.f, r_dy = 0.f, r_dz = 0.f, r_mu = 0.f, r_ni2s = 0.f, r_k = 0.f, r_invd = 0.f;
    if (tid < MM) {
        const int w = tid >> 5;
        const int nbraw = neigh[(size_t)atom * MM + tid];
        const bool valid = nbraw >= 0;
        const int nb = valid ? nbraw : 0;

        const float ax = coords[(size_t)atom * 3 + 0];
        const float ay = coords[(size_t)atom * 3 + 1];
        const float az = coords[(size_t)atom * 3 + 2];
        const size_t nbase = ((size_t)b * NN + nb) * 3;
        float dx = ax - coords[nbase + 0];
        float dy = ay - coords[nbase + 1];
        float dz = az - coords[nbase + 2];
        if (!valid) { dx = 1.0f; dy = 1.0f; dz = 1.0f; }

        const float d2 = dx*dx + dy*dy + dz*dz;
        const float d  = sqrtf(d2);
        const float sig2 = log1pf(2.0f / d2);
        const float mu   = logf(d) - 0.5f * sig2;
        const float dsw  = (d - 1.0f) * 0.2f;
        const float dsw2 = dsw * dsw;
        const float dsw3 = dsw2 * dsw;
        const float cut  = 1.0f - dsw3 * (10.0f - 15.0f*dsw + 6.0f*dsw2);

        const int z = charges[(size_t)b * NN + nb];
        my_sp = (z == 1) ? 0 : ((z == 6) ? 1 : ((z == 7) ? 2 : 3));

        r_dx = dx; r_dy = dy; r_dz = dz;
        r_mu = mu;
        r_ni2s = -HLOG2E / sig2;                                  // exp pre-scaled for ex2
        r_k    = valid ? (cut * rsqrtf(sig2) * (1.0f / SQRTPI_F)) : 0.0f;
        r_invd = valid ? (1.0f / d) : 0.0f;

        bm0 = __ballot_sync(0xffffffffu, my_sp == 0);
        bm1 = __ballot_sync(0xffffffffu, my_sp == 1);
        bm2 = __ballot_sync(0xffffffffu, my_sp == 2);
        bm3 = __ballot_sync(0xffffffffu, my_sp == 3);
        if ((tid & 31) == 0) {
            s_wcnt[w][0] = __popc(bm0);
            s_wcnt[w][1] = __popc(bm1);
            s_wcnt[w][2] = __popc(bm2);
            s_wcnt[w][3] = __popc(bm3);
        }
    }
    __syncthreads();

    if (tid == 0) {
        const int c0 = s_wcnt[0][0] + s_wcnt[1][0];
        const int c1 = s_wcnt[0][1] + s_wcnt[1][1];
        const int c2 = s_wcnt[0][2] + s_wcnt[1][2];
        const int c3 = s_wcnt[0][3] + s_wcnt[1][3];
        int s0 = 0;
        int s1 = (s0 + c0 + 3) & ~3;
        int s2 = (s1 + c1 + 3) & ~3;
        int s3 = (s2 + c2 + 3) & ~3;
        int s4 = (s3 + c3 + 3) & ~3;
        s_seg4[0] = s0; s_seg4[1] = s1; s_seg4[2] = s2; s_seg4[3] = s3; s_seg4[4] = s4;
    }
    __syncthreads();

    // ---- scatter to species-sorted, 4-aligned positions ----
    if (tid < MM) {
        const int w = tid >> 5;
        const int lane = tid & 31;
        const unsigned myb = (my_sp == 0) ? bm0 : ((my_sp == 1) ? bm1 : ((my_sp == 2) ? bm2 : bm3));
        int rank = __popc(myb & ((1u << lane) - 1u));
        if (w == 1) rank += s_wcnt[0][my_sp];
        const int pos = s_seg4[my_sp] + rank;
        s_nbx[pos] = r_dx; s_nby[pos] = r_dy; s_nbz[pos] = r_dz;
        s_mu[pos]  = r_mu; s_ni2s[pos] = r_ni2s;
        s_k[pos]   = r_k;  s_invd[pos] = r_invd;
    }
    __syncthreads();

    // ---- phase B ----
    // radial: threads [0,152) -> 2 threads per m (76 rows), 10 g's each
    if (tid < 2 * MM2) {
        const int m    = tid >> 1;
        const int half = tid & 1;
        const float mu   = s_mu[m];
        const float ni2s = s_ni2s[m];
        const float k    = s_k[m];
        const int g0 = half * 10;
        #pragma unroll
        for (int gg = 0; gg < 10; gg++) {
            const int g = g0 + gg;
            const float c = c_logoff[g] - mu;
            const float e = ex2f(c * c * ni2s);
            s_rad[g * MMR + m] = k * c_invoff[g] * e;
        }
    }
    // angular: threads [152, 152+76) -> one thread per m, 10 a's each
    else if (tid < 2 * MM2 + MM2) {
        const int m = tid - 2 * MM2;
        const float x = s_nbx[m], y = s_nby[m], zc = s_nbz[m];
        const float id = s_invd[m];
        const float i2 = id * id;
        const float i3 = i2 * id;
        const float i4 = i2 * i2;
        s_ang[0 * MMP + m] = i2;
        s_ang[1 * MMP + m] = i3 * x;
        s_ang[2 * MMP + m] = i3 * y;
        s_ang[3 * MMP + m] = i3 * zc;
        s_ang[4 * MMP + m] = i4 * x * x;
        s_ang[5 * MMP + m] = i4 * x * y;
        s_ang[6 * MMP + m] = i4 * y * y;
        s_ang[7 * MMP + m] = i4 * x * zc;
        s_ang[8 * MMP + m] = i4 * y * zc;
        s_ang[9 * MMP + m] = i4 * zc * zc;
    }
    __syncthreads();

    // ---- main loop: thread (a,g); ang via LDS.128 (broadcast-cheap),
    //      rad via scalar LDS from odd-stride rows (conflict-free) ----
    if (tid < NA * NG) {
        const int a = tid / NG;
        const int g = tid - a * NG;
        const float4* __restrict__ angp = (const float4*)(s_ang + a * MMP);
        const float*  __restrict__ radp = s_rad + g * MMR;
        const int e0 = s_seg4[1] >> 2;
        const int e1 = s_seg4[2] >> 2;
        const int e2 = s_seg4[3] >> 2;
        const int e3 = s_seg4[4] >> 2;

        float t0 = 0.f, t1 = 0.f, t2 = 0.f, t3 = 0.f;
        int c = 0;
        #pragma unroll 2
        for (; c < e0; ++c) {
            const float4 av = angp[c];
            const float* rp = radp + (c << 2);
            t0 = fmaf(av.x, rp[0], t0); t0 = fmaf(av.y, rp[1], t0);
            t0 = fmaf(av.z, rp[2], t0); t0 = fmaf(av.w, rp[3], t0);
        }
        #pragma unroll 2
        for (; c < e1; ++c) {
            const float4 av = angp[c];
            const float* rp = radp + (c << 2);
            t1 = fmaf(av.x, rp[0], t1); t1 = fmaf(av.y, rp[1], t1);
            t1 = fmaf(av.z, rp[2], t1); t1 = fmaf(av.w, rp[3], t1);
        }
        #pragma unroll 2
        for (; c < e2; ++c) {
            const float4 av = angp[c];
            const float* rp = radp + (c << 2);
            t2 = fmaf(av.x, rp[0], t2); t2 = fmaf(av.y, rp[1], t2);
            t2 = fmaf(av.z, rp[2], t2); t2 = fmaf(av.w, rp[3], t2);
        }
        #pragma unroll 2
        for (; c < e3; ++c) {
            const float4 av = angp[c];
            const float* rp = radp + (c << 2);
            t3 = fmaf(av.x, rp[0], t3); t3 = fmaf(av.y, rp[1], t3);
            t3 = fmaf(av.z, rp[2], t3); t3 = fmaf(av.w, rp[3], t3);
        }
        s_t[tid] = make_float4(t0, t1, t2, t3);
    }
    __syncthreads();

    // ---- epilogue: 600 outputs (scalar, as R3) ----
    for (int o = tid; o < FPS; o += 256) {
        const int g    = o % NG;
        const int rest = o / NG;
        const int mb   = rest % 10;
        const int l    = rest / 10;
        const int a0 = (l == 0) ? 0 : ((l == 1) ? 1 : 4);
        const int a1 = (l == 0) ? 1 : ((l == 1) ? 4 : 10);
        float val = 0.0f;
        if (mb < 4) {
            for (int a = a0; a < a1; a++) {
                const float4 t = s_t[a * NG + g];
                const float ts = pick4(t, mb);
                val = fmaf(c_angw[a] * ts, ts, val);
            }
        } else {
            const int cidx = mb - 4;
            const int i = c_ci[cidx], j = c_cj[cidx];
            for (int a = a0; a < a1; a++) {
                const float4 t = s_t[a * NG + g];
                val = fmaf(2.0f * c_angw[a] * pick4(t, i), pick4(t, j), val);
            }
        }
        outp[o] = val;
    }
}

extern "C" void kernel_launch(void* const* d_in, const int* in_sizes, int n_in,
                              void* d_out, int out_size) {
    const float* coords  = (const float*)d_in[0];
    const int*   charges = (const int*)d_in[1];
    const int*   counts  = (const int*)d_in[2];
    const int*   neigh   = (const int*)d_in[3];
    float* out = (float*)d_out;
    (void)n_in; (void)out_size;

    const int B = in_sizes[2];
    const int N = in_sizes[1] / B;
    dim3 grid(B * N);
    fp_kernel<<<grid, 256>>>(coords, charges, counts, neigh, out);
}

// round 9
// speedup vs baseline: 2.0415x; 1.2676x over previous
#include <cuda_runtime.h>
#include <math.h>

#define NN    128
#define MM    64
#define MM2   76            // padded neighbour capacity (segments 4-aligned)
#define MMP   76            // ang row stride in floats (16B multiple)
#define MMR   77            // rad row stride in floats (odd -> conflict-free scalar reads)
#define NG    20
#define NA    10
#define FPS   600
#define SPS   211           // species stride in s_ts (odd-ish -> low-conflict epilogue reads)

#define SQRTPI_F 1.7724538509055160273f
#define HLOG2E   0.72134752044448170368f   // 0.5 * log2(e)

__constant__ float c_angw[NA] = {1.f,1.f,1.f,1.f,1.f,2.f,1.f,2.f,2.f,1.f};
// unified epilogue tables: row mb -> (i, j, wm). mb 0..3 species (i=j=s, wm=1),
// mb 4..9 combos [(0,1),(0,2),(0,3),(1,2),(1,3),(2,3)] with wm=2.
__constant__ int   c_ei[10] = {0,1,2,3, 0,0,0,1,1,2};
__constant__ int   c_ej[10] = {0,1,2,3, 1,2,3,2,3,3};
__constant__ float c_ew[10] = {1.f,1.f,1.f,1.f, 2.f,2.f,2.f,2.f,2.f,2.f};

// log(0.3*(g+1)) and 1/(0.3*(g+1)), g=0..19
__constant__ float c_logoff[NG] = {
    -1.2039728043f, -0.5108256238f, -0.1053605157f,  0.1823215568f,
     0.4054651081f,  0.5877866649f,  0.7419373447f,  0.8754687374f,
     0.9932517730f,  1.0986122887f,  1.1939224685f,  1.2809338455f,
     1.3609765531f,  1.4350845253f,  1.5040773968f,  1.5686159179f,
     1.6292405397f,  1.6863989543f,  1.7404661748f,  1.7917594692f };
__constant__ float c_invoff[NG] = {
    3.3333333333f, 1.6666666667f, 1.1111111111f, 0.8333333333f,
    0.6666666667f, 0.5555555556f, 0.4761904762f, 0.4166666667f,
    0.3703703704f, 0.3333333333f, 0.3030303030f, 0.2777777778f,
    0.2564102564f, 0.2380952381f, 0.2222222222f, 0.2083333333f,
    0.1960784314f, 0.1851851852f, 0.1754385965f, 0.1666666667f };

__device__ __forceinline__ float ex2f(float x) {
    float y;
    asm("ex2.approx.ftz.f32 %0, %1;" : "=f"(y) : "f"(x));
    return y;
}

__global__ __launch_bounds__(256, 6)
void fp_kernel(const float* __restrict__ coords,
               const int*   __restrict__ charges,
               const int*   __restrict__ counts,
               const int*   __restrict__ neigh,
               float*       __restrict__ out)
{
    const int atom = blockIdx.x;
    const int b = atom >> 7;              // NN = 128
    const int n = atom & 127;
    const int tid = threadIdx.x;

    float* outp = out + (size_t)atom * FPS;

    if (n >= counts[b]) {
        for (int o = tid; o < FPS; o += 256) outp[o] = 0.0f;
        return;
    }

    __shared__ __align__(16) float s_rad[NG * MMR];   // [g][m], stride 77
    __shared__ __align__(16) float s_ang[NA * MMP];   // [a][m], stride 76
    __shared__ float s_ts[3 * SPS + NA * NG];         // [s][a][g], species stride 211
    __shared__ float s_nbx[MM2], s_nby[MM2], s_nbz[MM2];
    __shared__ float s_mu[MM2], s_ni2s[MM2], s_k[MM2], s_invd[MM2];
    __shared__ int   s_wcnt[2][4];
    __shared__ int   s_seg4[5];           // 4-aligned segment starts

    // ---- defaults for padded slots (rad -> 0, ang -> 0) ----
    if (tid < MM2) {
        s_mu[tid] = 0.f; s_ni2s[tid] = 0.f; s_k[tid] = 0.f; s_invd[tid] = 0.f;
        s_nbx[tid] = 0.f; s_nby[tid] = 0.f; s_nbz[tid] = 0.f;
    }

    // ---- phase A: per-neighbour scalars + species ballots ----
    int my_sp = 0;
    unsigned bm0 = 0, bm1 = 0, bm2 = 0, bm3 = 0;
    float r_dx = 0.f, r_dy = 0.f, r_dz = 0.f, r_mu = 0.f, r_ni2s = 0.f, r_k = 0.f, r_invd = 0.f;
    if (tid < MM) {
        const int w = tid >> 5;
        const int nbraw = neigh[(size_t)atom * MM + tid];
        const bool valid = nbraw >= 0;
        const int nb = valid ? nbraw : 0;

        const float ax = coords[(size_t)atom * 3 + 0];
        const float ay = coords[(size_t)atom * 3 + 1];
        const float az = coords[(size_t)atom * 3 + 2];
        const size_t nbase = ((size_t)b * NN + nb) * 3;
        float dx = ax - coords[nbase + 0];
        float dy = ay - coords[nbase + 1];
        float dz = az - coords[nbase + 2];
        if (!valid) { dx = 1.0f; dy = 1.0f; dz = 1.0f; }

        const float d2 = dx*dx + dy*dy + dz*dz;
        const float d  = sqrtf(d2);
        const float sig2 = log1pf(2.0f / d2);
        const float mu   = logf(d) - 0.5f * sig2;
        const float dsw  = (d - 1.0f) * 0.2f;
        const float dsw2 = dsw * dsw;
        const float dsw3 = dsw2 * dsw;
        const float cut  = 1.0f - dsw3 * (10.0f - 15.0f*dsw + 6.0f*dsw2);

        const int z = charges[(size_t)b * NN + nb];
        my_sp = (z == 1) ? 0 : ((z == 6) ? 1 : ((z == 7) ? 2 : 3));

        r_dx = dx; r_dy = dy; r_dz = dz;
        r_mu = mu;
        r_ni2s = -HLOG2E / sig2;                                  // exp pre-scaled for ex2
        r_k    = valid ? (cut * rsqrtf(sig2) * (1.0f / SQRTPI_F)) : 0.0f;
        r_invd = valid ? (1.0f / d) : 0.0f;

        bm0 = __ballot_sync(0xffffffffu, my_sp == 0);
        bm1 = __ballot_sync(0xffffffffu, my_sp == 1);
        bm2 = __ballot_sync(0xffffffffu, my_sp == 2);
        bm3 = __ballot_sync(0xffffffffu, my_sp == 3);
        if ((tid & 31) == 0) {
            s_wcnt[w][0] = __popc(bm0);
            s_wcnt[w][1] = __popc(bm1);
            s_wcnt[w][2] = __popc(bm2);
            s_wcnt[w][3] = __popc(bm3);
        }
    }
    __syncthreads();

    if (tid == 0) {
        const int c0 = s_wcnt[0][0] + s_wcnt[1][0];
        const int c1 = s_wcnt[0][1] + s_wcnt[1][1];
        const int c2 = s_wcnt[0][2] + s_wcnt[1][2];
        const int c3 = s_wcnt[0][3] + s_wcnt[1][3];
        int s0 = 0;
        int s1 = (s0 + c0 + 3) & ~3;
        int s2 = (s1 + c1 + 3) & ~3;
        int s3 = (s2 + c2 + 3) & ~3;
        int s4 = (s3 + c3 + 3) & ~3;
        s_seg4[0] = s0; s_seg4[1] = s1; s_seg4[2] = s2; s_seg4[3] = s3; s_seg4[4] = s4;
    }
    __syncthreads();

    // ---- scatter to species-sorted, 4-aligned positions ----
    if (tid < MM) {
        const int w = tid >> 5;
        const int lane = tid & 31;
        const unsigned myb = (my_sp == 0) ? bm0 : ((my_sp == 1) ? bm1 : ((my_sp == 2) ? bm2 : bm3));
        int rank = __popc(myb & ((1u << lane) - 1u));
        if (w == 1) rank += s_wcnt[0][my_sp];
        const int pos = s_seg4[my_sp] + rank;
        s_nbx[pos] = r_dx; s_nby[pos] = r_dy; s_nbz[pos] = r_dz;
        s_mu[pos]  = r_mu; s_ni2s[pos] = r_ni2s;
        s_k[pos]   = r_k;  s_invd[pos] = r_invd;
    }
    __syncthreads();

    // ---- phase B ----
    // radial: threads [0,152) -> 2 threads per m (76 rows), 10 g's each
    if (tid < 2 * MM2) {
        const int m    = tid >> 1;
        const int half = tid & 1;
        const float mu   = s_mu[m];
        const float ni2s = s_ni2s[m];
        const float k    = s_k[m];
        const int g0 = half * 10;
        #pragma unroll
        for (int gg = 0; gg < 10; gg++) {
            const int g = g0 + gg;
            const float c = c_logoff[g] - mu;
            const float e = ex2f(c * c * ni2s);
            s_rad[g * MMR + m] = k * c_invoff[g] * e;
        }
    }
    // angular: threads [152, 152+76) -> one thread per m, 10 a's each
    else if (tid < 2 * MM2 + MM2) {
        const int m = tid - 2 * MM2;
        const float x = s_nbx[m], y = s_nby[m], zc = s_nbz[m];
        const float id = s_invd[m];
        const float i2 = id * id;
        const float i3 = i2 * id;
        const float i4 = i2 * i2;
        s_ang[0 * MMP + m] = i2;
        s_ang[1 * MMP + m] = i3 * x;
        s_ang[2 * MMP + m] = i3 * y;
        s_ang[3 * MMP + m] = i3 * zc;
        s_ang[4 * MMP + m] = i4 * x * x;
        s_ang[5 * MMP + m] = i4 * x * y;
        s_ang[6 * MMP + m] = i4 * y * y;
        s_ang[7 * MMP + m] = i4 * x * zc;
        s_ang[8 * MMP + m] = i4 * y * zc;
        s_ang[9 * MMP + m] = i4 * zc * zc;
    }
    __syncthreads();

    // ---- main loop: thread (a,g); ang via LDS.128, rad scalar odd-stride ----
    if (tid < NA * NG) {
        const int a = tid / NG;
        const int g = tid - a * NG;
        const float4* __restrict__ angp = (const float4*)(s_ang + a * MMP);
        const float*  __restrict__ radp = s_rad + g * MMR;
        const int e0 = s_seg4[1] >> 2;
        const int e1 = s_seg4[2] >> 2;
        const int e2 = s_seg4[3] >> 2;
        const int e3 = s_seg4[4] >> 2;

        float t0 = 0.f, t1 = 0.f, t2 = 0.f, t3 = 0.f;
        int c = 0;
        #pragma unroll 2
        for (; c < e0; ++c) {
            const float4 av = angp[c];
            const float* rp = radp + (c << 2);
            t0 = fmaf(av.x, rp[0], t0); t0 = fmaf(av.y, rp[1], t0);
            t0 = fmaf(av.z, rp[2], t0); t0 = fmaf(av.w, rp[3], t0);
        }
        #pragma unroll 2
        for (; c < e1; ++c) {
            const float4 av = angp[c];
            const float* rp = radp + (c << 2);
            t1 = fmaf(av.x, rp[0], t1); t1 = fmaf(av.y, rp[1], t1);
            t1 = fmaf(av.z, rp[2], t1); t1 = fmaf(av.w, rp[3], t1);
        }
        #pragma unroll 2
        for (; c < e2; ++c) {
            const float4 av = angp[c];
            const float* rp = radp + (c << 2);
            t2 = fmaf(av.x, rp[0], t2); t2 = fmaf(av.y, rp[1], t2);
            t2 = fmaf(av.z, rp[2], t2); t2 = fmaf(av.w, rp[3], t2);
        }
        #pragma unroll 2
        for (; c < e3; ++c) {
            const float4 av = angp[c];
            const float* rp = radp + (c << 2);
            t3 = fmaf(av.x, rp[0], t3); t3 = fmaf(av.y, rp[1], t3);
            t3 = fmaf(av.z, rp[2], t3); t3 = fmaf(av.w, rp[3], t3);
        }
        // transposed store: [s][a][g], tid = a*NG+g, conflict-free per STS
        s_ts[0 * SPS + tid] = t0;
        s_ts[1 * SPS + tid] = t1;
        s_ts[2 * SPS + tid] = t2;
        s_ts[3 * SPS + tid] = t3;
    }
    __syncthreads();

    // ---- epilogue: thread (mb,g) computes its 3 l-outputs, branch/SEL-free ----
    if (tid < 200) {
        const int mb = tid / 20;
        const int g  = tid - mb * 20;
        const float wm = c_ew[mb];
        const float* __restrict__ ti = s_ts + c_ei[mb] * SPS + g;   // + a*20
        const float* __restrict__ tj = s_ts + c_ej[mb] * SPS + g;

        // l = 0: a = 0 (angw = 1)
        const float v0 = ti[0] * tj[0];
        // l = 1: a = 1..3 (angw = 1)
        float v1 = ti[20] * tj[20];
        v1 = fmaf(ti[40], tj[40], v1);
        v1 = fmaf(ti[60], tj[60], v1);
        // l = 2: a = 4..9 (angw = 1,2,1,2,2,1)
        float v2 = ti[80] * tj[80];
        v2 = fmaf(2.0f * ti[100], tj[100], v2);
        v2 = fmaf(ti[120], tj[120], v2);
        v2 = fmaf(2.0f * ti[140], tj[140], v2);
        v2 = fmaf(2.0f * ti[160], tj[160], v2);
        v2 = fmaf(ti[180], tj[180], v2);

        outp[tid]       = wm * v0;
        outp[200 + tid] = wm * v1;
        outp[400 + tid] = wm * v2;
    }
}

extern "C" void kernel_launch(void* const* d_in, const int* in_sizes, int n_in,
                              void* d_out, int out_size) {
    const float* coords  = (const float*)d_in[0];
    const int*   charges = (const int*)d_in[1];
    const int*   counts  = (const int*)d_in[2];
    const int*   neigh   = (const int*)d_in[3];
    float* out = (float*)d_out;
    (void)n_in; (void)out_size;

    const int B = in_sizes[2];
    const int N = in_sizes[1] / B;
    dim3 grid(B * N);
    fp_kernel<<<grid, 256>>>(coords, charges, counts, neigh, out);
}

// round 10
// speedup vs baseline: 2.1337x; 1.0452x over previous
#include <cuda_runtime.h>
#include <math.h>

#define NN    128
#define MM    64
#define MM2   76            // padded neighbour capacity (segments 4-aligned)
#define MMP   76            // ang row stride in floats (16B multiple)
#define MMR   77            // rad row stride in floats (odd -> conflict-free scalar reads)
#define NG    20
#define NA    10
#define FPS   600
#define SPS   211           // species stride in s_ts

#define RSQRTPI_F 0.56418958354775628695f
#define LN2_F     0.69314718055994530942f
#define HLOG2E    0.72134752044448170368f   // 0.5 * log2(e)

// log(0.3*(g+1)) and 1/(0.3*(g+1)), g=0..19
__constant__ float c_logoff[NG] = {
    -1.2039728043f, -0.5108256238f, -0.1053605157f,  0.1823215568f,
     0.4054651081f,  0.5877866649f,  0.7419373447f,  0.8754687374f,
     0.9932517730f,  1.0986122887f,  1.1939224685f,  1.2809338455f,
     1.3609765531f,  1.4350845253f,  1.5040773968f,  1.5686159179f,
     1.6292405397f,  1.6863989543f,  1.7404661748f,  1.7917594692f };
__constant__ float c_invoff[NG] = {
    3.3333333333f, 1.6666666667f, 1.1111111111f, 0.8333333333f,
    0.6666666667f, 0.5555555556f, 0.4761904762f, 0.4166666667f,
    0.3703703704f, 0.3333333333f, 0.3030303030f, 0.2777777778f,
    0.2564102564f, 0.2380952381f, 0.2222222222f, 0.2083333333f,
    0.1960784314f, 0.1851851852f, 0.1754385965f, 0.1666666667f };

// unified epilogue tables: mb 0..3 species (i=j=s, wm=1); mb 4..9 combos wm=2
__constant__ int   c_ei[10] = {0,1,2,3, 0,0,0,1,1,2};
__constant__ int   c_ej[10] = {0,1,2,3, 1,2,3,2,3,3};
__constant__ float c_ew[10] = {1.f,1.f,1.f,1.f, 2.f,2.f,2.f,2.f,2.f,2.f};

__device__ __forceinline__ float ex2f(float x)  { float y; asm("ex2.approx.ftz.f32 %0, %1;"   : "=f"(y) : "f"(x)); return y; }
__device__ __forceinline__ float lg2f(float x)  { float y; asm("lg2.approx.ftz.f32 %0, %1;"   : "=f"(y) : "f"(x)); return y; }
__device__ __forceinline__ float rcpf(float x)  { float y; asm("rcp.approx.ftz.f32 %0, %1;"   : "=f"(y) : "f"(x)); return y; }
__device__ __forceinline__ float rsqf(float x)  { float y; asm("rsqrt.approx.ftz.f32 %0, %1;" : "=f"(y) : "f"(x)); return y; }

__global__ __launch_bounds__(256, 7)
void fp_kernel(const float* __restrict__ coords,
               const int*   __restrict__ charges,
               const int*   __restrict__ counts,
               const int*   __restrict__ neigh,
               float*       __restrict__ out)
{
    const int atom = blockIdx.x;
    const int b = atom >> 7;              // NN = 128
    const int n = atom & 127;
    const int tid = threadIdx.x;

    float* outp = out + (size_t)atom * FPS;

    if (n >= counts[b]) {
        for (int o = tid; o < FPS; o += 256) outp[o] = 0.0f;
        return;
    }

    __shared__ __align__(16) float s_rad[NG * MMR];   // [g][m], stride 77
    __shared__ __align__(16) float s_ang[NA * MMP];   // [a][m], stride 76
    __shared__ float s_ts[3 * SPS + NA * NG];         // [s][a][g], species stride 211
    __shared__ float s_nbx[MM2], s_nby[MM2], s_nbz[MM2];
    __shared__ float s_mu[MM2], s_ni2s[MM2], s_k[MM2], s_invd[MM2];
    __shared__ int   s_wcnt[2][4];
    __shared__ int   s_seg4[5];           // 4-aligned segment starts

    // ---- defaults for padded slots (rad -> 0, ang -> 0) ----
    if (tid < MM2) {
        s_mu[tid] = 0.f; s_ni2s[tid] = 0.f; s_k[tid] = 0.f; s_invd[tid] = 0.f;
        s_nbx[tid] = 0.f; s_nby[tid] = 0.f; s_nbz[tid] = 0.f;
    }

    // ---- phase A: per-neighbour scalars + species ballots (threads 0..63) ----
    int my_sp = 0;
    unsigned bm0 = 0, bm1 = 0, bm2 = 0, bm3 = 0;
    float r_dx = 0.f, r_dy = 0.f, r_dz = 0.f, r_mu = 0.f, r_ni2s = 0.f, r_k = 0.f, r_invd = 0.f;
    if (tid < MM) {
        const int w = tid >> 5;
        const int nbraw = neigh[(size_t)atom * MM + tid];
        const bool valid = nbraw >= 0;
        const int nb = valid ? nbraw : 0;

        const float ax = coords[(size_t)atom * 3 + 0];
        const float ay = coords[(size_t)atom * 3 + 1];
        const float az = coords[(size_t)atom * 3 + 2];
        const size_t nbase = ((size_t)b * NN + nb) * 3;
        float dx = ax - coords[nbase + 0];
        float dy = ay - coords[nbase + 1];
        float dz = az - coords[nbase + 2];
        if (!valid) { dx = 1.0f; dy = 1.0f; dz = 1.0f; }

        const float d2   = dx*dx + dy*dy + dz*dz;
        const float ivd  = rsqf(d2);                              // 1/d
        const float d    = d2 * ivd;
        const float rd2  = ivd * ivd;                             // 1/d^2
        const float sig2 = LN2_F * lg2f(fmaf(2.0f, rd2, 1.0f));   // log1p(2/d^2)
        const float mu   = fmaf(0.5f * LN2_F, lg2f(d2), -0.5f * sig2);
        const float dsw  = (d - 1.0f) * 0.2f;
        const float dsw2 = dsw * dsw;
        const float cut  = 1.0f - dsw2 * dsw * (10.0f - 15.0f*dsw + 6.0f*dsw2);

        const int z = charges[(size_t)b * NN + nb];
        my_sp = (z == 1) ? 0 : ((z == 6) ? 1 : ((z == 7) ? 2 : 3));

        r_dx = dx; r_dy = dy; r_dz = dz;
        r_mu = mu;
        r_ni2s = -HLOG2E * rcpf(sig2);                            // exp pre-scaled for ex2
        r_k    = valid ? (cut * rsqf(sig2) * RSQRTPI_F) : 0.0f;
        r_invd = valid ? ivd : 0.0f;

        bm0 = __ballot_sync(0xffffffffu, my_sp == 0);
        bm1 = __ballot_sync(0xffffffffu, my_sp == 1);
        bm2 = __ballot_sync(0xffffffffu, my_sp == 2);
        bm3 = __ballot_sync(0xffffffffu, my_sp == 3);
        if ((tid & 31) == 0) {
            s_wcnt[w][0] = __popc(bm0);
            s_wcnt[w][1] = __popc(bm1);
            s_wcnt[w][2] = __popc(bm2);
            s_wcnt[w][3] = __popc(bm3);
        }
    }
    __syncthreads();

    // ---- scatter to species-sorted 4-aligned slots (segments computed locally) ----
    if (tid < MM) {
        const int c0 = s_wcnt[0][0] + s_wcnt[1][0];
        const int c1 = s_wcnt[0][1] + s_wcnt[1][1];
        const int c2 = s_wcnt[0][2] + s_wcnt[1][2];
        const int c3 = s_wcnt[0][3] + s_wcnt[1][3];
        const int s1 = (c0 + 3) & ~3;
        const int s2 = (s1 + c1 + 3) & ~3;
        const int s3 = (s2 + c2 + 3) & ~3;
        const int base = (my_sp == 0) ? 0 : ((my_sp == 1) ? s1 : ((my_sp == 2) ? s2 : s3));
        const int w = tid >> 5;
        const int lane = tid & 31;
        const unsigned myb = (my_sp == 0) ? bm0 : ((my_sp == 1) ? bm1 : ((my_sp == 2) ? bm2 : bm3));
        int rank = __popc(myb & ((1u << lane) - 1u));
        if (w == 1) rank += s_wcnt[0][my_sp];
        const int pos = base + rank;
        s_nbx[pos] = r_dx; s_nby[pos] = r_dy; s_nbz[pos] = r_dz;
        s_mu[pos]  = r_mu; s_ni2s[pos] = r_ni2s;
        s_k[pos]   = r_k;  s_invd[pos] = r_invd;
        if (tid == 0) {
            s_seg4[0] = 0;
            s_seg4[1] = s1;
            s_seg4[2] = s2;
            s_seg4[3] = s3;
            s_seg4[4] = (s3 + c3 + 3) & ~3;
        }
    }
    __syncthreads();

    // ---- phase B ----
    // radial: threads [0,152) -> 2 threads per m (76 rows), 10 g's each
    if (tid < 2 * MM2) {
        const int m    = tid >> 1;
        const int half = tid & 1;
        const float mu   = s_mu[m];
        const float ni2s = s_ni2s[m];
        const float k    = s_k[m];
        const int g0 = half * 10;
        #pragma unroll
        for (int gg = 0; gg < 10; gg++) {
            const int g = g0 + gg;
            const float c = c_logoff[g] - mu;
            const float e = ex2f(c * c * ni2s);
            s_rad[g * MMR + m] = k * c_invoff[g] * e;
        }
    }
    // angular: threads [152, 152+76) -> one thread per m, 10 a's each
    else if (tid < 2 * MM2 + MM2) {
        const int m = tid - 2 * MM2;
        const float x = s_nbx[m], y = s_nby[m], zc = s_nbz[m];
        const float id = s_invd[m];
        const float i2 = id * id;
        const float i3 = i2 * id;
        const float i4 = i2 * i2;
        s_ang[0 * MMP + m] = i2;
        s_ang[1 * MMP + m] = i3 * x;
        s_ang[2 * MMP + m] = i3 * y;
        s_ang[3 * MMP + m] = i3 * zc;
        s_ang[4 * MMP + m] = i4 * x * x;
        s_ang[5 * MMP + m] = i4 * x * y;
        s_ang[6 * MMP + m] = i4 * y * y;
        s_ang[7 * MMP + m] = i4 * x * zc;
        s_ang[8 * MMP + m] = i4 * y * zc;
        s_ang[9 * MMP + m] = i4 * zc * zc;
    }
    __syncthreads();

    // ---- main loop: thread (a,g); ang via LDS.128, rad scalar odd-stride ----
    if (tid < NA * NG) {
        const int a = tid / NG;
        const int g = tid - a * NG;
        const float4* __restrict__ angp = (const float4*)(s_ang + a * MMP);
        const float*  __restrict__ radp = s_rad + g * MMR;
        const int e0 = s_seg4[1] >> 2;
        const int e1 = s_seg4[2] >> 2;
        const int e2 = s_seg4[3] >> 2;
        const int e3 = s_seg4[4] >> 2;

        float t0 = 0.f, t1 = 0.f, t2 = 0.f, t3 = 0.f;
        int c = 0;
        #pragma unroll 2
        for (; c < e0; ++c) {
            const float4 av = angp[c];
            const float* rp = radp + (c << 2);
            t0 = fmaf(av.x, rp[0], t0); t0 = fmaf(av.y, rp[1], t0);
            t0 = fmaf(av.z, rp[2], t0); t0 = fmaf(av.w, rp[3], t0);
        }
        #pragma unroll 2
        for (; c < e1; ++c) {
            const float4 av = angp[c];
            const float* rp = radp + (c << 2);
            t1 = fmaf(av.x, rp[0], t1); t1 = fmaf(av.y, rp[1], t1);
            t1 = fmaf(av.z, rp[2], t1); t1 = fmaf(av.w, rp[3], t1);
        }
        #pragma unroll 2
        for (; c < e2; ++c) {
            const float4 av = angp[c];
            const float* rp = radp + (c << 2);
            t2 = fmaf(av.x, rp[0], t2); t2 = fmaf(av.y, rp[1], t2);
            t2 = fmaf(av.z, rp[2], t2); t2 = fmaf(av.w, rp[3], t2);
        }
        #pragma unroll 2
        for (; c < e3; ++c) {
            const float4 av = angp[c];
            const float* rp = radp + (c << 2);
            t3 = fmaf(av.x, rp[0], t3); t3 = fmaf(av.y, rp[1], t3);
            t3 = fmaf(av.z, rp[2], t3); t3 = fmaf(av.w, rp[3], t3);
        }
        // transposed store: [s][a][g], tid = a*NG+g
        s_ts[0 * SPS + tid] = t0;
        s_ts[1 * SPS + tid] = t1;
        s_ts[2 * SPS + tid] = t2;
        s_ts[3 * SPS + tid] = t3;
    }
    __syncthreads();

    // ---- epilogue: thread (mb,g) computes its 3 l-outputs, branch/SEL-free ----
    if (tid < 200) {
        const int mb = tid / 20;
        const int g  = tid - mb * 20;
        const float wm = c_ew[mb];
        const float* __restrict__ ti = s_ts + c_ei[mb] * SPS + g;   // + a*20
        const float* __restrict__ tj = s_ts + c_ej[mb] * SPS + g;

        // l = 0: a = 0 (angw = 1)
        const float v0 = ti[0] * tj[0];
        // l = 1: a = 1..3 (angw = 1)
        float v1 = ti[20] * tj[20];
        v1 = fmaf(ti[40], tj[40], v1);
        v1 = fmaf(ti[60], tj[60], v1);
        // l = 2: a = 4..9 (angw = 1,2,1,2,2,1)
        float v2 = ti[80] * tj[80];
        v2 = fmaf(2.0f * ti[100], tj[100], v2);
        v2 = fmaf(ti[120], tj[120], v2);
        v2 = fmaf(2.0f * ti[140], tj[140], v2);
        v2 = fmaf(2.0f * ti[160], tj[160], v2);
        v2 = fmaf(ti[180], tj[180], v2);

        outp[tid]       = wm * v0;
        outp[200 + tid] = wm * v1;
        outp[400 + tid] = wm * v2;
    }
}

extern "C" void kernel_launch(void* const* d_in, const int* in_sizes, int n_in,
                              void* d_out, int out_size) {
    const float* coords  = (const float*)d_in[0];
    const int*   charges = (const int*)d_in[1];
    const int*   counts  = (const int*)d_in[2];
    const int*   neigh   = (const int*)d_in[3];
    float* out = (float*)d_out;
    (void)n_in; (void)out_size;

    const int B = in_sizes[2];
    const int N = in_sizes[1] / B;
    dim3 grid(B * N);
    fp_kernel<<<grid, 256>>>(coords, charges, counts, neigh, out);
}

// round 11
// speedup vs baseline: 2.2336x; 1.0468x over previous
#include <cuda_runtime.h>
#include <math.h>

#define NN    128
#define MM    64
#define MM2   76            // padded neighbour capacity (segments 4-aligned)
#define MMP   76            // ang row stride in floats (16B multiple)
#define MMR   77            // rad row stride in floats (odd -> conflict-free scalar reads)
#define NG    20
#define NA    10
#define FPS   600
#define SPS   211           // species stride in s_ts
#define TSSZ  (3 * SPS + NA * NG)

#define RSQRTPI_F 0.56418958354775628695f
#define LN2_F     0.69314718055994530942f
#define HLOG2E    0.72134752044448170368f   // 0.5 * log2(e)

// log(0.3*(g+1)) and 1/(0.3*(g+1)), g=0..19
__constant__ float c_logoff[NG] = {
    -1.2039728043f, -0.5108256238f, -0.1053605157f,  0.1823215568f,
     0.4054651081f,  0.5877866649f,  0.7419373447f,  0.8754687374f,
     0.9932517730f,  1.0986122887f,  1.1939224685f,  1.2809338455f,
     1.3609765531f,  1.4350845253f,  1.5040773968f,  1.5686159179f,
     1.6292405397f,  1.6863989543f,  1.7404661748f,  1.7917594692f };
__constant__ float c_invoff[NG] = {
    3.3333333333f, 1.6666666667f, 1.1111111111f, 0.8333333333f,
    0.6666666667f, 0.5555555556f, 0.4761904762f, 0.4166666667f,
    0.3703703704f, 0.3333333333f, 0.3030303030f, 0.2777777778f,
    0.2564102564f, 0.2380952381f, 0.2222222222f, 0.2083333333f,
    0.1960784314f, 0.1851851852f, 0.1754385965f, 0.1666666667f };

// unified epilogue tables: mb 0..3 species (i=j=s, wm=1); mb 4..9 combos wm=2
__constant__ int   c_ei[10] = {0,1,2,3, 0,0,0,1,1,2};
__constant__ int   c_ej[10] = {0,1,2,3, 1,2,3,2,3,3};
__constant__ float c_ew[10] = {1.f,1.f,1.f,1.f, 2.f,2.f,2.f,2.f,2.f,2.f};

__device__ __forceinline__ float ex2f(float x)  { float y; asm("ex2.approx.ftz.f32 %0, %1;"   : "=f"(y) : "f"(x)); return y; }
__device__ __forceinline__ float lg2f(float x)  { float y; asm("lg2.approx.ftz.f32 %0, %1;"   : "=f"(y) : "f"(x)); return y; }
__device__ __forceinline__ float rcpf(float x)  { float y; asm("rcp.approx.ftz.f32 %0, %1;"   : "=f"(y) : "f"(x)); return y; }
__device__ __forceinline__ float rsqf(float x)  { float y; asm("rsqrt.approx.ftz.f32 %0, %1;" : "=f"(y) : "f"(x)); return y; }

__global__ __launch_bounds__(256, 6)
void fp_kernel(const float* __restrict__ coords,
               const int*   __restrict__ charges,
               const int*   __restrict__ counts,
               const int*   __restrict__ neigh,
               float*       __restrict__ out)
{
    const int half = threadIdx.x >> 7;        // which atom in this block
    const int h    = threadIdx.x & 127;       // local tid within the half
    const int atom = blockIdx.x * 2 + half;
    const int b = atom >> 7;                  // NN = 128
    const int n = atom & 127;

    float* outp = out + (size_t)atom * FPS;
    const bool masked = (n >= counts[b]);

    __shared__ __align__(16) float s_rad[2][NG * MMR];   // [g][m], stride 77
    __shared__ __align__(16) float s_ang[2][NA * MMP];   // [a][m], stride 76
    __shared__ float s_ts[2][TSSZ];                      // [s][a][g], stride 211
    __shared__ float s_nbx[2][MM2], s_nby[2][MM2], s_nbz[2][MM2];
    __shared__ float s_mu[2][MM2], s_ni2s[2][MM2], s_k[2][MM2], s_invd[2][MM2];
    __shared__ int   s_wcnt[2][2][4];
    __shared__ int   s_seg4[2][5];

    // ---- defaults for padded slots (k=0 -> rad=0; invd=0 -> ang=0) ----
    if (h < MM2) {
        s_mu[half][h] = 0.f; s_ni2s[half][h] = 0.f; s_k[half][h] = 0.f; s_invd[half][h] = 0.f;
        s_nbx[half][h] = 0.f; s_nby[half][h] = 0.f; s_nbz[half][h] = 0.f;
    }

    // ---- phase A: per-neighbour scalars + species ballots (h 0..63) ----
    int my_sp = 0;
    unsigned bm0 = 0, bm1 = 0, bm2 = 0, bm3 = 0;
    float r_dx = 0.f, r_dy = 0.f, r_dz = 0.f, r_mu = 0.f, r_ni2s = 0.f, r_k = 0.f, r_invd = 0.f;
    if (!masked && h < MM) {
        const int w = h >> 5;
        const int nbraw = neigh[(size_t)atom * MM + h];
        const bool valid = nbraw >= 0;
        const int nb = valid ? nbraw : 0;

        const float ax = coords[(size_t)atom * 3 + 0];
        const float ay = coords[(size_t)atom * 3 + 1];
        const float az = coords[(size_t)atom * 3 + 2];
        const size_t nbase = ((size_t)b * NN + nb) * 3;
        float dx = ax - coords[nbase + 0];
        float dy = ay - coords[nbase + 1];
        float dz = az - coords[nbase + 2];
        if (!valid) { dx = 1.0f; dy = 1.0f; dz = 1.0f; }

        const float d2   = dx*dx + dy*dy + dz*dz;
        const float ivd  = rsqf(d2);                              // 1/d
        const float d    = d2 * ivd;
        const float rd2  = ivd * ivd;                             // 1/d^2
        const float sig2 = LN2_F * lg2f(fmaf(2.0f, rd2, 1.0f));   // log1p(2/d^2)
        const float mu   = fmaf(0.5f * LN2_F, lg2f(d2), -0.5f * sig2);
        const float dsw  = (d - 1.0f) * 0.2f;
        const float dsw2 = dsw * dsw;
        const float cut  = 1.0f - dsw2 * dsw * (10.0f - 15.0f*dsw + 6.0f*dsw2);

        const int z = charges[(size_t)b * NN + nb];
        my_sp = (z == 1) ? 0 : ((z == 6) ? 1 : ((z == 7) ? 2 : 3));

        r_dx = dx; r_dy = dy; r_dz = dz;
        r_mu = mu;
        r_ni2s = -HLOG2E * rcpf(sig2);                            // exp pre-scaled for ex2
        r_k    = valid ? (cut * rsqf(sig2) * RSQRTPI_F) : 0.0f;
        r_invd = valid ? ivd : 0.0f;

        bm0 = __ballot_sync(0xffffffffu, my_sp == 0);
        bm1 = __ballot_sync(0xffffffffu, my_sp == 1);
        bm2 = __ballot_sync(0xffffffffu, my_sp == 2);
        bm3 = __ballot_sync(0xffffffffu, my_sp == 3);
        if ((h & 31) == 0) {
            s_wcnt[half][w][0] = __popc(bm0);
            s_wcnt[half][w][1] = __popc(bm1);
            s_wcnt[half][w][2] = __popc(bm2);
            s_wcnt[half][w][3] = __popc(bm3);
        }
    }
    __syncthreads();

    // ---- scatter to species-sorted 4-aligned slots; publish segment ends ----
    if (!masked && h < MM) {
        const int c0 = s_wcnt[half][0][0] + s_wcnt[half][1][0];
        const int c1 = s_wcnt[half][0][1] + s_wcnt[half][1][1];
        const int c2 = s_wcnt[half][0][2] + s_wcnt[half][1][2];
        const int c3 = s_wcnt[half][0][3] + s_wcnt[half][1][3];
        const int s1 = (c0 + 3) & ~3;
        const int s2 = (s1 + c1 + 3) & ~3;
        const int s3 = (s2 + c2 + 3) & ~3;
        const int base = (my_sp == 0) ? 0 : ((my_sp == 1) ? s1 : ((my_sp == 2) ? s2 : s3));
        const int w = h >> 5;
        const int lane = h & 31;
        const unsigned myb = (my_sp == 0) ? bm0 : ((my_sp == 1) ? bm1 : ((my_sp == 2) ? bm2 : bm3));
        int rank = __popc(myb & ((1u << lane) - 1u));
        if (w == 1) rank += s_wcnt[half][0][my_sp];
        const int pos = base + rank;
        s_nbx[half][pos] = r_dx; s_nby[half][pos] = r_dy; s_nbz[half][pos] = r_dz;
        s_mu[half][pos]  = r_mu; s_ni2s[half][pos] = r_ni2s;
        s_k[half][pos]   = r_k;  s_invd[half][pos] = r_invd;
        if (h == 0) {
            s_seg4[half][0] = 0;
            s_seg4[half][1] = s1;
            s_seg4[half][2] = s2;
            s_seg4[half][3] = s3;
            s_seg4[half][4] = (s3 + c3 + 3) & ~3;
        }
    }
    __syncthreads();

    // ---- phase B: h < 76, one m each: 20 radial entries + 10 angular entries ----
    if (!masked && h < MM2) {
        const int m = h;
        const float mu   = s_mu[half][m];
        const float ni2s = s_ni2s[half][m];
        const float k    = s_k[half][m];
        float* radb = s_rad[half];
        #pragma unroll
        for (int g = 0; g < NG; g++) {
            const float c = c_logoff[g] - mu;
            const float e = ex2f(c * c * ni2s);
            radb[g * MMR + m] = k * c_invoff[g] * e;
        }
        const float x = s_nbx[half][m], y = s_nby[half][m], zc = s_nbz[half][m];
        const float id = s_invd[half][m];
        const float i2 = id * id;
        const float i3 = i2 * id;
        const float i4 = i2 * i2;
        float* angb = s_ang[half];
        angb[0 * MMP + m] = i2;
        angb[1 * MMP + m] = i3 * x;
        angb[2 * MMP + m] = i3 * y;
        angb[3 * MMP + m] = i3 * zc;
        angb[4 * MMP + m] = i4 * x * x;
        angb[5 * MMP + m] = i4 * x * y;
        angb[6 * MMP + m] = i4 * y * y;
        angb[7 * MMP + m] = i4 * x * zc;
        angb[8 * MMP + m] = i4 * y * zc;
        angb[9 * MMP + m] = i4 * zc * zc;
    }
    __syncthreads();

    // ---- main loop: h < 100, thread (a, g) computes g and g+10; ang shared ----
    if (!masked && h < 100) {
        const int a = h / 10;
        const int g = h - a * 10;
        const float4* __restrict__ angp = (const float4*)(s_ang[half] + a * MMP);
        const float*  __restrict__ radp = s_rad[half] + g * MMR;   // g ; g+10 at +770
        const int e0 = s_seg4[half][1] >> 2;
        const int e1 = s_seg4[half][2] >> 2;
        const int e2 = s_seg4[half][3] >> 2;
        const int e3 = s_seg4[half][4] >> 2;

        float tA0=0.f, tA1=0.f, tA2=0.f, tA3=0.f;
        float tB0=0.f, tB1=0.f, tB2=0.f, tB3=0.f;
        int c = 0;
        #pragma unroll 2
        for (; c < e0; ++c) {
            const float4 av = angp[c];
            const float* p0 = radp + (c << 2);
            tA0 = fmaf(av.x, p0[0], tA0);   tA0 = fmaf(av.y, p0[1], tA0);
            tA0 = fmaf(av.z, p0[2], tA0);   tA0 = fmaf(av.w, p0[3], tA0);
            tB0 = fmaf(av.x, p0[770], tB0); tB0 = fmaf(av.y, p0[771], tB0);
            tB0 = fmaf(av.z, p0[772], tB0); tB0 = fmaf(av.w, p0[773], tB0);
        }
        #pragma unroll 2
        for (; c < e1; ++c) {
            const float4 av = angp[c];
            const float* p0 = radp + (c << 2);
            tA1 = fmaf(av.x, p0[0], tA1);   tA1 = fmaf(av.y, p0[1], tA1);
            tA1 = fmaf(av.z, p0[2], tA1);   tA1 = fmaf(av.w, p0[3], tA1);
            tB1 = fmaf(av.x, p0[770], tB1); tB1 = fmaf(av.y, p0[771], tB1);
            tB1 = fmaf(av.z, p0[772], tB1); tB1 = fmaf(av.w, p0[773], tB1);
        }
        #pragma unroll 2
        for (; c < e2; ++c) {
            const float4 av = angp[c];
            const float* p0 = radp + (c << 2);
            tA2 = fmaf(av.x, p0[0], tA2);   tA2 = fmaf(av.y, p0[1], tA2);
            tA2 = fmaf(av.z, p0[2], tA2);   tA2 = fmaf(av.w, p0[3], tA2);
            tB2 = fmaf(av.x, p0[770], tB2); tB2 = fmaf(av.y, p0[771], tB2);
            tB2 = fmaf(av.z, p0[772], tB2); tB2 = fmaf(av.w, p0[773], tB2);
        }
        #pragma unroll 2
        for (; c < e3; ++c) {
            const float4 av = angp[c];
            const float* p0 = radp + (c << 2);
            tA3 = fmaf(av.x, p0[0], tA3);   tA3 = fmaf(av.y, p0[1], tA3);
            tA3 = fmaf(av.z, p0[2], tA3);   tA3 = fmaf(av.w, p0[3], tA3);
            tB3 = fmaf(av.x, p0[770], tB3); tB3 = fmaf(av.y, p0[771], tB3);
            tB3 = fmaf(av.z, p0[772], tB3); tB3 = fmaf(av.w, p0[773], tB3);
        }
        float* tsb = s_ts[half];
        const int idxA = a * NG + g;
        tsb[0 * SPS + idxA]      = tA0;
        tsb[1 * SPS + idxA]      = tA1;
        tsb[2 * SPS + idxA]      = tA2;
        tsb[3 * SPS + idxA]      = tA3;
        tsb[0 * SPS + idxA + 10] = tB0;
        tsb[1 * SPS + idxA + 10] = tB1;
        tsb[2 * SPS + idxA + 10] = tB2;
        tsb[3 * SPS + idxA + 10] = tB3;
    }
    __syncthreads();

    // ---- epilogue: h < 100, thread (mb, g) does g and g+10, 6 outputs ----
    if (!masked && h < 100) {
        const int mb = h / 10;
        const int g0 = h - mb * 10;
        const float wm = c_ew[mb];
        const float* __restrict__ tib = s_ts[half] + c_ei[mb] * SPS;
        const float* __restrict__ tjb = s_ts[half] + c_ej[mb] * SPS;

        #pragma unroll
        for (int gg = 0; gg < 2; gg++) {
            const int g = g0 + gg * 10;
            const float* ti = tib + g;
            const float* tj = tjb + g;
            const float v0 = ti[0] * tj[0];
            float v1 = ti[20] * tj[20];
            v1 = fmaf(ti[40], tj[40], v1);
            v1 = fmaf(ti[60], tj[60], v1);
            float v2 = ti[80] * tj[80];
            v2 = fmaf(2.0f * ti[100], tj[100], v2);
            v2 = fmaf(ti[120], tj[120], v2);
            v2 = fmaf(2.0f * ti[140], tj[140], v2);
            v2 = fmaf(2.0f * ti[160], tj[160], v2);
            v2 = fmaf(ti[180], tj[180], v2);
            const int o = mb * 20 + g;
            outp[o]       = wm * v0;
            outp[200 + o] = wm * v1;
            outp[400 + o] = wm * v2;
        }
    }

    // ---- masked atoms: zero-fill ----
    if (masked) {
        for (int o = h; o < FPS; o += 128) outp[o] = 0.0f;
    }
}

extern "C" void kernel_launch(void* const* d_in, const int* in_sizes, int n_in,
                              void* d_out, int out_size) {
    const float* coords  = (const float*)d_in[0];
    const int*   charges = (const int*)d_in[1];
    const int*   counts  = (const int*)d_in[2];
    const int*   neigh   = (const int*)d_in[3];
    float* out = (float*)d_out;
    (void)n_in; (void)out_size;

    const int B = in_sizes[2];
    const int N = in_sizes[1] / B;
    dim3 grid((B * N) / 2);
    fp_kernel<<<grid, 256>>>(coords, charges, counts, neigh, out);
}

// round 12
// speedup vs baseline: 2.5049x; 1.1215x over previous
#include <cuda_runtime.h>
#include <math.h>

#define NN    128
#define MM    64
#define MM2   76            // padded neighbour capacity (segments 4-aligned)
#define MMP   76            // ang row stride in floats (16B multiple)
#define MMR   77            // rad row stride in floats (odd -> conflict-free scalar reads)
#define NG    20
#define NA    10
#define FPS   600
#define SPS   211           // species stride in s_ts
#define TSSZ  (3 * SPS + NA * NG)

#define RSQRTPI_F 0.56418958354775628695f
#define LN2_F     0.69314718055994530942f
#define HLOG2E    0.72134752044448170368f   // 0.5 * log2(e)

// log(0.3*(g+1)) and 1/(0.3*(g+1)), g=0..19
__constant__ float c_logoff[NG] = {
    -1.2039728043f, -0.5108256238f, -0.1053605157f,  0.1823215568f,
     0.4054651081f,  0.5877866649f,  0.7419373447f,  0.8754687374f,
     0.9932517730f,  1.0986122887f,  1.1939224685f,  1.2809338455f,
     1.3609765531f,  1.4350845253f,  1.5040773968f,  1.5686159179f,
     1.6292405397f,  1.6863989543f,  1.7404661748f,  1.7917594692f };
__constant__ float c_invoff[NG] = {
    3.3333333333f, 1.6666666667f, 1.1111111111f, 0.8333333333f,
    0.6666666667f, 0.5555555556f, 0.4761904762f, 0.4166666667f,
    0.3703703704f, 0.3333333333f, 0.3030303030f, 0.2777777778f,
    0.2564102564f, 0.2380952381f, 0.2222222222f, 0.2083333333f,
    0.1960784314f, 0.1851851852f, 0.1754385965f, 0.1666666667f };

// unified epilogue tables: mb 0..3 species (i=j=s, wm=1); mb 4..9 combos wm=2
__constant__ int   c_ei[10] = {0,1,2,3, 0,0,0,1,1,2};
__constant__ int   c_ej[10] = {0,1,2,3, 1,2,3,2,3,3};
__constant__ float c_ew[10] = {1.f,1.f,1.f,1.f, 2.f,2.f,2.f,2.f,2.f,2.f};

__device__ __forceinline__ float ex2f(float x)  { float y; asm("ex2.approx.ftz.f32 %0, %1;"   : "=f"(y) : "f"(x)); return y; }
__device__ __forceinline__ float lg2f(float x)  { float y; asm("lg2.approx.ftz.f32 %0, %1;"   : "=f"(y) : "f"(x)); return y; }
__device__ __forceinline__ float rcpf(float x)  { float y; asm("rcp.approx.ftz.f32 %0, %1;"   : "=f"(y) : "f"(x)); return y; }
__device__ __forceinline__ float rsqf(float x)  { float y; asm("rsqrt.approx.ftz.f32 %0, %1;" : "=f"(y) : "f"(x)); return y; }

__global__ __launch_bounds__(256, 6)
void fp_kernel(const float* __restrict__ coords,
               const int*   __restrict__ charges,
               const int*   __restrict__ counts,
               const int*   __restrict__ neigh,
               float*       __restrict__ out)
{
    const int half = threadIdx.x >> 7;        // which atom in this block
    const int h    = threadIdx.x & 127;       // local tid within the half
    const int atom = blockIdx.x * 2 + half;
    const int b = atom >> 7;                  // NN = 128
    const int n = atom & 127;

    float* outp = out + (size_t)atom * FPS;
    const bool masked = (n >= counts[b]);

    __shared__ __align__(16) float s_rad[2][NG * MMR];   // [g][m], stride 77
    __shared__ __align__(16) float s_ang[2][NA * MMP];   // [a][m], stride 76
    __shared__ float s_ts[2][TSSZ];                      // [s][a][g], stride 211
    __shared__ float s_nbx[2][MM2], s_nby[2][MM2], s_nbz[2][MM2];
    __shared__ float s_mu[2][MM2], s_ni2s[2][MM2], s_k[2][MM2], s_invd[2][MM2];
    __shared__ int   s_wcnt[2][2][4];
    __shared__ int   s_seg4[2][5];

    // ---- defaults for padded slots (k=0 -> rad=0; invd=0 -> ang=0) ----
    if (h < MM2) {
        s_mu[half][h] = 0.f; s_ni2s[half][h] = 0.f; s_k[half][h] = 0.f; s_invd[half][h] = 0.f;
        s_nbx[half][h] = 0.f; s_nby[half][h] = 0.f; s_nbz[half][h] = 0.f;
    }

    // ---- phase A: per-neighbour scalars + species ballots (h 0..63) ----
    int my_sp = 0;
    unsigned bm0 = 0, bm1 = 0, bm2 = 0, bm3 = 0;
    float r_dx = 0.f, r_dy = 0.f, r_dz = 0.f, r_mu = 0.f, r_ni2s = 0.f, r_k = 0.f, r_invd = 0.f;
    if (!masked && h < MM) {
        const int w = h >> 5;
        const int nbraw = neigh[(size_t)atom * MM + h];
        const bool valid = nbraw >= 0;
        const int nb = valid ? nbraw : 0;

        const float ax = coords[(size_t)atom * 3 + 0];
        const float ay = coords[(size_t)atom * 3 + 1];
        const float az = coords[(size_t)atom * 3 + 2];
        const size_t nbase = ((size_t)b * NN + nb) * 3;
        float dx = ax - coords[nbase + 0];
        float dy = ay - coords[nbase + 1];
        float dz = az - coords[nbase + 2];
        if (!valid) { dx = 1.0f; dy = 1.0f; dz = 1.0f; }

        const float d2   = dx*dx + dy*dy + dz*dz;
        const float ivd  = rsqf(d2);                              // 1/d
        const float d    = d2 * ivd;
        const float rd2  = ivd * ivd;                             // 1/d^2
        const float sig2 = LN2_F * lg2f(fmaf(2.0f, rd2, 1.0f));   // log1p(2/d^2)
        const float mu   = fmaf(0.5f * LN2_F, lg2f(d2), -0.5f * sig2);
        const float dsw  = (d - 1.0f) * 0.2f;
        const float dsw2 = dsw * dsw;
        const float cut  = 1.0f - dsw2 * dsw * (10.0f - 15.0f*dsw + 6.0f*dsw2);

        const int z = charges[(size_t)b * NN + nb];
        my_sp = (z == 1) ? 0 : ((z == 6) ? 1 : ((z == 7) ? 2 : 3));

        r_dx = dx; r_dy = dy; r_dz = dz;
        r_mu = mu;
        r_ni2s = -HLOG2E * rcpf(sig2);                            // exp pre-scaled for ex2
        r_k    = valid ? (cut * rsqf(sig2) * RSQRTPI_F) : 0.0f;
        r_invd = valid ? ivd : 0.0f;

        bm0 = __ballot_sync(0xffffffffu, my_sp == 0);
        bm1 = __ballot_sync(0xffffffffu, my_sp == 1);
        bm2 = __ballot_sync(0xffffffffu, my_sp == 2);
        bm3 = __ballot_sync(0xffffffffu, my_sp == 3);
        if ((h & 31) == 0) {
            s_wcnt[half][w][0] = __popc(bm0);
            s_wcnt[half][w][1] = __popc(bm1);
            s_wcnt[half][w][2] = __popc(bm2);
            s_wcnt[half][w][3] = __popc(bm3);
        }
    }
    __syncthreads();

    // ---- scatter to species-sorted 4-aligned slots; publish segment ends ----
    if (!masked && h < MM) {
        const int c0 = s_wcnt[half][0][0] + s_wcnt[half][1][0];
        const int c1 = s_wcnt[half][0][1] + s_wcnt[half][1][1];
        const int c2 = s_wcnt[half][0][2] + s_wcnt[half][1][2];
        const int c3 = s_wcnt[half][0][3] + s_wcnt[half][1][3];
        const int s1 = (c0 + 3) & ~3;
        const int s2 = (s1 + c1 + 3) & ~3;
        const int s3 = (s2 + c2 + 3) & ~3;
        const int base = (my_sp == 0) ? 0 : ((my_sp == 1) ? s1 : ((my_sp == 2) ? s2 : s3));
        const int w = h >> 5;
        const int lane = h & 31;
        const unsigned myb = (my_sp == 0) ? bm0 : ((my_sp == 1) ? bm1 : ((my_sp == 2) ? bm2 : bm3));
        int rank = __popc(myb & ((1u << lane) - 1u));
        if (w == 1) rank += s_wcnt[half][0][my_sp];
        const int pos = base + rank;
        s_nbx[half][pos] = r_dx; s_nby[half][pos] = r_dy; s_nbz[half][pos] = r_dz;
        s_mu[half][pos]  = r_mu; s_ni2s[half][pos] = r_ni2s;
        s_k[half][pos]   = r_k;  s_invd[half][pos] = r_invd;
        if (h == 0) {
            s_seg4[half][0] = 0;
            s_seg4[half][1] = s1;
            s_seg4[half][2] = s2;
            s_seg4[half][3] = s3;
            s_seg4[half][4] = (s3 + c3 + 3) & ~3;
        }
    }
    __syncthreads();

    // ---- phase B: h < 76, one m each: 20 radial entries + 10 angular entries ----
    if (!masked && h < MM2) {
        const int m = h;
        const float mu   = s_mu[half][m];
        const float ni2s = s_ni2s[half][m];
        const float k    = s_k[half][m];
        float* radb = s_rad[half];
        #pragma unroll
        for (int g = 0; g < NG; g++) {
            const float c = c_logoff[g] - mu;
            const float e = ex2f(c * c * ni2s);
            radb[g * MMR + m] = k * c_invoff[g] * e;
        }
        const float x = s_nbx[half][m], y = s_nby[half][m], zc = s_nbz[half][m];
        const float id = s_invd[half][m];
        const float i2 = id * id;
        const float i3 = i2 * id;
        const float i4 = i2 * i2;
        float* angb = s_ang[half];
        angb[0 * MMP + m] = i2;
        angb[1 * MMP + m] = i3 * x;
        angb[2 * MMP + m] = i3 * y;
        angb[3 * MMP + m] = i3 * zc;
        angb[4 * MMP + m] = i4 * x * x;
        angb[5 * MMP + m] = i4 * x * y;
        angb[6 * MMP + m] = i4 * y * y;
        angb[7 * MMP + m] = i4 * x * zc;
        angb[8 * MMP + m] = i4 * y * zc;
        angb[9 * MMP + m] = i4 * zc * zc;
    }
    __syncthreads();

    // ---- main loop: h < 50, thread (a0, g0) computes 2x2 tile
    //      {a0, a0+5} x {g0, g0+10}; 4 accumulators reused across species ----
    if (!masked && h < 50) {
        const int a = h / 10;          // 0..4
        const int g = h - a * 10;      // 0..9
        const float4* __restrict__ angp0 = (const float4*)(s_ang[half] + a * MMP);
        const float4* __restrict__ angp1 = (const float4*)(s_ang[half] + (a + 5) * MMP);
        const float*  __restrict__ radp  = s_rad[half] + g * MMR;   // g+10 rows at +770

        float* tsb = s_ts[half];
        const int idx = a * NG + g;
        int c = 0;
        #pragma unroll
        for (int s = 0; s < 4; s++) {
            const int e = s_seg4[half][s + 1] >> 2;
            float t00 = 0.f, t01 = 0.f, t10 = 0.f, t11 = 0.f;
            #pragma unroll 2
            for (; c < e; ++c) {
                const float4 av0 = angp0[c];
                const float4 av1 = angp1[c];
                const float* rp = radp + (c << 2);
                const float r0x = rp[0],   r0y = rp[1],   r0z = rp[2],   r0w = rp[3];
                const float r1x = rp[770], r1y = rp[771], r1z = rp[772], r1w = rp[773];
                t00 = fmaf(av0.x, r0x, t00); t00 = fmaf(av0.y, r0y, t00);
                t00 = fmaf(av0.z, r0z, t00); t00 = fmaf(av0.w, r0w, t00);
                t01 = fmaf(av0.x, r1x, t01); t01 = fmaf(av0.y, r1y, t01);
                t01 = fmaf(av0.z, r1z, t01); t01 = fmaf(av0.w, r1w, t01);
                t10 = fmaf(av1.x, r0x, t10); t10 = fmaf(av1.y, r0y, t10);
                t10 = fmaf(av1.z, r0z, t10); t10 = fmaf(av1.w, r0w, t10);
                t11 = fmaf(av1.x, r1x, t11); t11 = fmaf(av1.y, r1y, t11);
                t11 = fmaf(av1.z, r1z, t11); t11 = fmaf(av1.w, r1w, t11);
            }
            tsb[s * SPS + idx]       = t00;   // (a,   g)
            tsb[s * SPS + idx + 10]  = t01;   // (a,   g+10)
            tsb[s * SPS + idx + 100] = t10;   // (a+5, g)
            tsb[s * SPS + idx + 110] = t11;   // (a+5, g+10)
        }
    }
    __syncthreads();

    // ---- epilogue: h < 100, thread (mb, g) does g and g+10, 6 outputs ----
    if (!masked && h < 100) {
        const int mb = h / 10;
        const int g0 = h - mb * 10;
        const float wm = c_ew[mb];
        const float* __restrict__ tib = s_ts[half] + c_ei[mb] * SPS;
        const float* __restrict__ tjb = s_ts[half] + c_ej[mb] * SPS;

        #pragma unroll
        for (int gg = 0; gg < 2; gg++) {
            const int g = g0 + gg * 10;
            const float* ti = tib + g;
            const float* tj = tjb + g;
            const float v0 = ti[0] * tj[0];
            float v1 = ti[20] * tj[20];
            v1 = fmaf(ti[40], tj[40], v1);
            v1 = fmaf(ti[60], tj[60], v1);
            float v2 = ti[80] * tj[80];
            v2 = fmaf(2.0f * ti[100], tj[100], v2);
            v2 = fmaf(ti[120], tj[120], v2);
            v2 = fmaf(2.0f * ti[140], tj[140], v2);
            v2 = fmaf(2.0f * ti[160], tj[160], v2);
            v2 = fmaf(ti[180], tj[180], v2);
            const int o = mb * 20 + g;
            outp[o]       = wm * v0;
            outp[200 + o] = wm * v1;
            outp[400 + o] = wm * v2;
        }
    }

    // ---- masked atoms: zero-fill ----
    if (masked) {
        for (int o = h; o < FPS; o += 128) outp[o] = 0.0f;
    }
}

extern "C" void kernel_launch(void* const* d_in, const int* in_sizes, int n_in,
                              void* d_out, int out_size) {
    const float* coords  = (const float*)d_in[0];
    const int*   charges = (const int*)d_in[1];
    const int*   counts  = (const int*)d_in[2];
    const int*   neigh   = (const int*)d_in[3];
    float* out = (float*)d_out;
    (void)n_in; (void)out_size;

    const int B = in_sizes[2];
    const int N = in_sizes[1] / B;
    dim3 grid((B * N) / 2);
    fp_kernel<<<grid, 256>>>(coords, charges, counts, neigh, out);
}